// round 5
// baseline (speedup 1.0000x reference)
#include <cuda_runtime.h>
#include <math.h>

#define N_NODES 4096
#define WORDS   64
#define HID     256
#define VOCAB   50257
#define NCLASS  4
#define N_LEAF  2048

// ---------------- device scratch (static: no allocations allowed) ----------------
__device__ float    g_ET[(size_t)VOCAB * HID];   // E transposed: [VOCAB][HID]  (51.5 MB)
__device__ float    g_X [N_NODES * HID];         // gathered embeddings
__device__ float    g_WX[N_NODES * 3 * HID];     // [n][ z(256) | r(256) | h(256) ]
__device__ float    g_UZP[HID * HID];            // U_z k-packed:   float4 idx (k/4)*HID + t  = U_z[t][4k'..4k'+3]
__device__ float    g_URP[HID * HID];
__device__ float    g_UHP[HID * HID];
__device__ float    g_H [N_NODES * HID];         // node hidden states
__device__ unsigned g_flag[N_NODES];             // node-done flags
__device__ float    g_red[32 * HID];             // leaf-max partials

// ---------------- kernels ----------------

__global__ void k_zero_flags() {
    int i = blockIdx.x * blockDim.x + threadIdx.x;
    if (i < N_NODES) g_flag[i] = (i == 0) ? 1u : 0u;  // node 0 produced by gather (earlier launch)
}

// Tiled transpose E (HID, VOCAB) -> g_ET (VOCAB, HID)
__global__ void k_transposeE(const float* __restrict__ E) {
    __shared__ float tile[32][33];
    int v0 = blockIdx.x * 32;
    int h0 = blockIdx.y * 32;
    int x = threadIdx.x, y = threadIdx.y;  // block (32,8)
    #pragma unroll
    for (int j = 0; j < 32; j += 8) {
        int v = v0 + x;
        if (v < VOCAB) tile[y + j][x] = E[(size_t)(h0 + y + j) * VOCAB + v];
    }
    __syncthreads();
    #pragma unroll
    for (int j = 0; j < 32; j += 8) {
        int v = v0 + y + j;
        if (v < VOCAB) g_ET[(size_t)v * HID + h0 + x] = tile[x][y + j];
    }
}

// Pack U matrices into k-packed transposed layout for coalesced float4 matvec loads.
__global__ void k_packU(const float* __restrict__ Uz,
                        const float* __restrict__ Ur,
                        const float* __restrict__ Uh) {
    int gid = blockIdx.x * blockDim.x + threadIdx.x;   // 3*65536 total
    if (gid >= 3 * HID * HID) return;
    int m   = gid / (HID * HID);
    int idx = gid % (HID * HID);
    int t = idx / HID;
    int k = idx % HID;
    const float* src = (m == 0) ? Uz : (m == 1) ? Ur : Uh;
    float*       dst = (m == 0) ? g_UZP : (m == 1) ? g_URP : g_UHP;
    dst[(k >> 2) * (HID * 4) + t * 4 + (k & 3)] = src[t * HID + k];
}

// X[n][t] = sum_w ET[tree[n][w]][t];  also seeds h[0] = X[0]
__global__ __launch_bounds__(HID) void k_gather(const int* __restrict__ tree) {
    int n = blockIdx.x;
    int t = threadIdx.x;
    __shared__ int w[WORDS];
    if (t < WORDS) w[t] = tree[n * WORDS + t];
    __syncthreads();
    float acc = 0.f;
    #pragma unroll 8
    for (int i = 0; i < WORDS; i++)
        acc += g_ET[(size_t)w[i] * HID + t];
    g_X[n * HID + t] = acc;
    if (n == 0) g_H[t] = acc;
}

// WX = X @ [Wz;Wr;Wh]^T  : (4096 x 768), K = 256.  64x64 tile, 4x4 micro.
#define GTM 64
#define GTN 64
#define GTK 32
__global__ __launch_bounds__(256) void k_gemm(const float* __restrict__ Wz,
                                              const float* __restrict__ Wr,
                                              const float* __restrict__ Wh) {
    __shared__ float As[GTK][65];   // [k][m], pad 65 -> conflict-free transposed stores
    __shared__ float Bs[GTK][65];   // [k][j]
    int mB = blockIdx.x;            // 0..63
    int jB = blockIdx.y;            // 0..11
    int tid = threadIdx.x;
    int tm = tid >> 4;              // 0..15
    int tn = tid & 15;              // 0..15

    int gate = (jB * GTN) >> 8;     // each 64-col tile lies in one gate
    const float* W = (gate == 0) ? Wz : (gate == 1) ? Wr : Wh;
    int jrow0 = jB * GTN - gate * HID;

    int lrow = tid >> 3;            // 0..31 (two passes for 64 rows)
    int lq   = tid & 7;             // float4 column 0..7 within 32-float k tile

    float acc[4][4];
    #pragma unroll
    for (int i = 0; i < 4; i++)
        #pragma unroll
        for (int j = 0; j < 4; j++) acc[i][j] = 0.f;

    for (int kt = 0; kt < HID; kt += GTK) {
        // load A tile (rows of X), transpose into As[k][m]
        #pragma unroll
        for (int p = 0; p < 2; p++) {
            int r = lrow + p * 32;
            float4 a = *reinterpret_cast<const float4*>(&g_X[(mB * GTM + r) * HID + kt + lq * 4]);
            As[lq * 4 + 0][r] = a.x; As[lq * 4 + 1][r] = a.y;
            As[lq * 4 + 2][r] = a.z; As[lq * 4 + 3][r] = a.w;
            float4 b = *reinterpret_cast<const float4*>(&W[(jrow0 + r) * HID + kt + lq * 4]);
            Bs[lq * 4 + 0][r] = b.x; Bs[lq * 4 + 1][r] = b.y;
            Bs[lq * 4 + 2][r] = b.z; Bs[lq * 4 + 3][r] = b.w;
        }
        __syncthreads();
        #pragma unroll
        for (int kk = 0; kk < GTK; kk++) {
            float a0 = As[kk][tm * 4 + 0], a1 = As[kk][tm * 4 + 1];
            float a2 = As[kk][tm * 4 + 2], a3 = As[kk][tm * 4 + 3];
            float b0 = Bs[kk][tn * 4 + 0], b1 = Bs[kk][tn * 4 + 1];
            float b2 = Bs[kk][tn * 4 + 2], b3 = Bs[kk][tn * 4 + 3];
            acc[0][0] = fmaf(a0, b0, acc[0][0]); acc[0][1] = fmaf(a0, b1, acc[0][1]);
            acc[0][2] = fmaf(a0, b2, acc[0][2]); acc[0][3] = fmaf(a0, b3, acc[0][3]);
            acc[1][0] = fmaf(a1, b0, acc[1][0]); acc[1][1] = fmaf(a1, b1, acc[1][1]);
            acc[1][2] = fmaf(a1, b2, acc[1][2]); acc[1][3] = fmaf(a1, b3, acc[1][3]);
            acc[2][0] = fmaf(a2, b0, acc[2][0]); acc[2][1] = fmaf(a2, b1, acc[2][1]);
            acc[2][2] = fmaf(a2, b2, acc[2][2]); acc[2][3] = fmaf(a2, b3, acc[2][3]);
            acc[3][0] = fmaf(a3, b0, acc[3][0]); acc[3][1] = fmaf(a3, b1, acc[3][1]);
            acc[3][2] = fmaf(a3, b2, acc[3][2]); acc[3][3] = fmaf(a3, b3, acc[3][3]);
        }
        __syncthreads();
    }
    #pragma unroll
    for (int i = 0; i < 4; i++) {
        int m = mB * GTM + tm * 4 + i;
        #pragma unroll
        for (int j = 0; j < 4; j++)
            g_WX[m * (3 * HID) + jB * GTN + tn * 4 + j] = acc[i][j];
    }
}

// Dependency-driven GRU wavefront: one CTA per node (bid+1), spins on parent flag.
// Forward progress: parent has smaller node index == smaller blockIdx, dispatched earlier.
__global__ __launch_bounds__(HID) void k_gru(const int* __restrict__ edge,
                                             const float* __restrict__ bz,
                                             const float* __restrict__ br,
                                             const float* __restrict__ bh) {
    int node = blockIdx.x + 1;
    int t = threadIdx.x;
    int p = edge[node * 2];   // parent

    __shared__ float ph[HID];
    __shared__ float pr[HID];

    if (t == 0) {
        volatile unsigned* fp = &g_flag[p];
        while (*fp == 0u) __nanosleep(40);
        __threadfence();   // acquire: producer's h stores (ordered before its fence+flag) now visible
    }
    __syncthreads();

    // fresh parent state from L2 (bypass L1: other CTAs on this SM never cached stale h[p])
    float phv = __ldcg(&g_H[p * HID + t]);
    ph[t] = phv;
    __syncthreads();

    const float4* UZ = reinterpret_cast<const float4*>(g_UZP);
    const float4* UR = reinterpret_cast<const float4*>(g_URP);
    const float4* UH = reinterpret_cast<const float4*>(g_UHP);

    float az = bz[t];
    float ar = br[t];
    #pragma unroll 8
    for (int kq = 0; kq < HID / 4; kq++) {
        float4 uz = UZ[kq * HID + t];
        float4 ur = UR[kq * HID + t];
        float p0 = ph[kq * 4 + 0], p1 = ph[kq * 4 + 1];
        float p2 = ph[kq * 4 + 2], p3 = ph[kq * 4 + 3];
        az = fmaf(uz.x, p0, az); az = fmaf(uz.y, p1, az);
        az = fmaf(uz.z, p2, az); az = fmaf(uz.w, p3, az);
        ar = fmaf(ur.x, p0, ar); ar = fmaf(ur.y, p1, ar);
        ar = fmaf(ur.z, p2, ar); ar = fmaf(ur.w, p3, ar);
    }
    float wzx = g_WX[node * (3 * HID) + t];
    float wrx = g_WX[node * (3 * HID) + HID + t];
    float whx = g_WX[node * (3 * HID) + 2 * HID + t];
    float z = 1.f / (1.f + __expf(-(wzx + az)));
    float r = 1.f / (1.f + __expf(-(wrx + ar)));
    pr[t] = phv * r;
    __syncthreads();

    float ah = bh[t];
    #pragma unroll 8
    for (int kq = 0; kq < HID / 4; kq++) {
        float4 uh = UH[kq * HID + t];
        float q0 = pr[kq * 4 + 0], q1 = pr[kq * 4 + 1];
        float q2 = pr[kq * 4 + 2], q3 = pr[kq * 4 + 3];
        ah = fmaf(uh.x, q0, ah); ah = fmaf(uh.y, q1, ah);
        ah = fmaf(uh.z, q2, ah); ah = fmaf(uh.w, q3, ah);
    }
    float c = tanhf(whx + ah);
    float h = z * phv + (1.f - z) * c;
    g_H[node * HID + t] = h;
    __syncthreads();
    if (t == 0) {
        __threadfence();                       // release h stores to GPU scope
        atomicExch(&g_flag[node], 1u);
    }
}

// 32 partial leaf-max blocks
__global__ __launch_bounds__(HID) void k_leafmax(const int* __restrict__ leaf) {
    int b = blockIdx.x;
    int t = threadIdx.x;
    float m = -INFINITY;
    for (int i = b; i < N_LEAF; i += 32) {
        int n = leaf[i];
        m = fmaxf(m, g_H[n * HID + t]);
    }
    g_red[b * HID + t] = m;
}

__global__ __launch_bounds__(HID) void k_final(const float* __restrict__ Wout,
                                               const float* __restrict__ bout,
                                               const float* __restrict__ y,
                                               float* __restrict__ out, int out_size) {
    __shared__ float f[HID];
    __shared__ float red[HID];
    __shared__ float logits[NCLASS];
    int t = threadIdx.x;
    float m = g_red[t];
    #pragma unroll
    for (int b = 1; b < 32; b++) m = fmaxf(m, g_red[b * HID + t]);
    f[t] = m;
    __syncthreads();
    for (int c = 0; c < NCLASS; c++) {
        red[t] = Wout[c * HID + t] * f[t];
        __syncthreads();
        for (int s = HID / 2; s > 0; s >>= 1) {
            if (t < s) red[t] += red[t + s];
            __syncthreads();
        }
        if (t == 0) logits[c] = red[0] + bout[c];
        __syncthreads();
    }
    if (t == 0) {
        float mx = logits[0];
        for (int c = 1; c < NCLASS; c++) mx = fmaxf(mx, logits[c]);
        float e[NCLASS], s = 0.f;
        for (int c = 0; c < NCLASS; c++) { e[c] = expf(logits[c] - mx); s += e[c]; }
        float loss = 0.f;
        for (int c = 0; c < NCLASS; c++) {
            float pred = e[c] / s;
            float d = y[c] - pred;
            loss += d * d;
            if (c < out_size) out[c] = pred;
        }
        if (out_size > NCLASS) out[NCLASS] = loss;
    }
    // zero-fill any extra output slots
    for (int i = NCLASS + 1 + t; i < out_size; i += HID) out[i] = 0.f;
}

// ---------------- launch ----------------
extern "C" void kernel_launch(void* const* d_in, const int* in_sizes, int n_in,
                              void* d_out, int out_size) {
    const int*   tree  = (const int*)  d_in[0];
    const int*   edge  = (const int*)  d_in[1];
    const int*   leaf  = (const int*)  d_in[2];
    const float* y     = (const float*)d_in[3];
    const float* E     = (const float*)d_in[4];
    const float* W_z   = (const float*)d_in[5];
    const float* U_z   = (const float*)d_in[6];
    const float* b_z   = (const float*)d_in[7];
    const float* W_r   = (const float*)d_in[8];
    const float* U_r   = (const float*)d_in[9];
    const float* b_r   = (const float*)d_in[10];
    const float* W_h   = (const float*)d_in[11];
    const float* U_h   = (const float*)d_in[12];
    const float* b_h   = (const float*)d_in[13];
    const float* W_out = (const float*)d_in[14];
    const float* b_out = (const float*)d_in[15];
    float* out = (float*)d_out;

    k_zero_flags<<<(N_NODES + 255) / 256, 256>>>();

    dim3 tb(32, 8);
    dim3 tg((VOCAB + 31) / 32, HID / 32);
    k_transposeE<<<tg, tb>>>(E);

    k_packU<<<(3 * HID * HID + 255) / 256, 256>>>(U_z, U_r, U_h);

    k_gather<<<N_NODES, HID>>>(tree);

    dim3 gg(N_NODES / GTM, (3 * HID) / GTN);
    k_gemm<<<gg, 256>>>(W_z, W_r, W_h);

    k_gru<<<N_NODES - 1, HID>>>(edge, b_z, b_r, b_h);

    k_leafmax<<<32, HID>>>(leaf);
    k_final<<<1, HID>>>(W_out, b_out, y, out, out_size);
}

// round 6
// speedup vs baseline: 1.9034x; 1.9034x over previous
#include <cuda_runtime.h>
#include <math.h>

#define N_NODES 4096
#define WORDS   64
#define HID     256
#define VOCAB   50257
#define NCLASS  4
#define N_LEAF  2048

// ---------------- device scratch (static: no allocations allowed) ----------------
__device__ float    g_ET[(size_t)VOCAB * HID];   // E transposed: [VOCAB][HID]
__device__ float    g_X [N_NODES * HID];         // gathered embeddings
__device__ float    g_WX[N_NODES * 3 * HID];     // [n][ z | r | h ]
__device__ float    g_UZP[HID * HID];            // packed U_z (quarter-split layout, see k_packU)
__device__ float    g_URP[HID * HID];
__device__ float    g_UHP[HID * HID];
__device__ float    g_H [N_NODES * HID];         // node hidden states
__device__ float    g_PR[N_NODES * HID];         // published ph*r quarters (intra-node exchange)
__device__ unsigned g_flag[N_NODES];             // node-done counters (4 = complete)
__device__ unsigned g_exc[N_NODES];              // intra-node exchange counters
__device__ float    g_red[32 * HID];             // leaf-max partials

// ---------------- helpers ----------------
__device__ __forceinline__ unsigned ld_acq(const unsigned* p) {
    unsigned v;
    asm volatile("ld.acquire.gpu.global.u32 %0, [%1];" : "=r"(v) : "l"(p) : "memory");
    return v;
}
__device__ __forceinline__ unsigned long long pk2(float a, float b) {
    unsigned long long r;
    asm("mov.b64 %0, {%1, %2};" : "=l"(r) : "f"(a), "f"(b));
    return r;
}
__device__ __forceinline__ unsigned long long ffma2(unsigned long long a, unsigned long long b,
                                                    unsigned long long c) {
    unsigned long long d;
    asm("fma.rn.f32x2 %0, %1, %2, %3;" : "=l"(d) : "l"(a), "l"(b), "l"(c));
    return d;
}
__device__ __forceinline__ float hsum2(unsigned long long a) {
    float lo, hi;
    asm("mov.b64 {%0, %1}, %2;" : "=f"(lo), "=f"(hi) : "l"(a));
    return lo + hi;
}

// ---------------- kernels ----------------

__global__ void k_zero_flags() {
    int i = blockIdx.x * blockDim.x + threadIdx.x;
    if (i < N_NODES) {
        g_flag[i] = (i == 0) ? 4u : 0u;   // node 0 produced by gather
        g_exc[i] = 0u;
    }
}

// Tiled transpose E (HID, VOCAB) -> g_ET (VOCAB, HID)
__global__ void k_transposeE(const float* __restrict__ E) {
    __shared__ float tile[32][33];
    int v0 = blockIdx.x * 32;
    int h0 = blockIdx.y * 32;
    int x = threadIdx.x, y = threadIdx.y;  // block (32,8)
    #pragma unroll
    for (int j = 0; j < 32; j += 8) {
        int v = v0 + x;
        if (v < VOCAB) tile[y + j][x] = E[(size_t)(h0 + y + j) * VOCAB + v];
    }
    __syncthreads();
    #pragma unroll
    for (int j = 0; j < 32; j += 8) {
        int v = v0 + y + j;
        if (v < VOCAB) g_ET[(size_t)v * HID + h0 + x] = tile[x][y + j];
    }
}

// Pack U matrices for the quarter-split GRU:
// thread (o, ks) of node-quarter q reads float4 at ((q*4+ks)*16 + kq)*64 + o
//   containing U[t=q*64+o][k = ks*64 + kq*4 .. +3]
__global__ void k_packU(const float* __restrict__ Uz,
                        const float* __restrict__ Ur,
                        const float* __restrict__ Uh) {
    int gid = blockIdx.x * blockDim.x + threadIdx.x;
    if (gid >= 3 * HID * HID) return;
    int m   = gid >> 16;
    int idx = gid & 65535;
    int t = idx >> 8;
    int k = idx & 255;
    int q = t >> 6, o = t & 63;
    int ks = k >> 6, kk = k & 63, kq = kk >> 2, j = kk & 3;
    int dst = (((q * 4 + ks) * 16 + kq) * 64 + o) * 4 + j;
    const float* src = (m == 0) ? Uz : (m == 1) ? Ur : Uh;
    float*       d   = (m == 0) ? g_UZP : (m == 1) ? g_URP : g_UHP;
    d[dst] = src[t * HID + k];
}

// X[n][t] = sum_w ET[tree[n][w]][t];  also seeds h[0] = X[0]
__global__ __launch_bounds__(HID) void k_gather(const int* __restrict__ tree) {
    int n = blockIdx.x;
    int t = threadIdx.x;
    __shared__ int w[WORDS];
    if (t < WORDS) w[t] = tree[n * WORDS + t];
    __syncthreads();
    float acc = 0.f;
    #pragma unroll 8
    for (int i = 0; i < WORDS; i++)
        acc += g_ET[(size_t)w[i] * HID + t];
    g_X[n * HID + t] = acc;
    if (n == 0) g_H[t] = acc;
}

// WX = X @ [Wz;Wr;Wh]^T  : (4096 x 768), K = 256.  64x64 tile, 4x4 micro.
#define GTM 64
#define GTN 64
#define GTK 32
__global__ __launch_bounds__(256) void k_gemm(const float* __restrict__ Wz,
                                              const float* __restrict__ Wr,
                                              const float* __restrict__ Wh) {
    __shared__ float As[GTK][65];
    __shared__ float Bs[GTK][65];
    int mB = blockIdx.x;
    int jB = blockIdx.y;
    int tid = threadIdx.x;
    int tm = tid >> 4;
    int tn = tid & 15;

    int gate = (jB * GTN) >> 8;
    const float* W = (gate == 0) ? Wz : (gate == 1) ? Wr : Wh;
    int jrow0 = jB * GTN - gate * HID;

    int lrow = tid >> 3;
    int lq   = tid & 7;

    float acc[4][4];
    #pragma unroll
    for (int i = 0; i < 4; i++)
        #pragma unroll
        for (int j = 0; j < 4; j++) acc[i][j] = 0.f;

    for (int kt = 0; kt < HID; kt += GTK) {
        #pragma unroll
        for (int p = 0; p < 2; p++) {
            int r = lrow + p * 32;
            float4 a = *reinterpret_cast<const float4*>(&g_X[(mB * GTM + r) * HID + kt + lq * 4]);
            As[lq * 4 + 0][r] = a.x; As[lq * 4 + 1][r] = a.y;
            As[lq * 4 + 2][r] = a.z; As[lq * 4 + 3][r] = a.w;
            float4 b = *reinterpret_cast<const float4*>(&W[(jrow0 + r) * HID + kt + lq * 4]);
            Bs[lq * 4 + 0][r] = b.x; Bs[lq * 4 + 1][r] = b.y;
            Bs[lq * 4 + 2][r] = b.z; Bs[lq * 4 + 3][r] = b.w;
        }
        __syncthreads();
        #pragma unroll
        for (int kk = 0; kk < GTK; kk++) {
            float a0 = As[kk][tm * 4 + 0], a1 = As[kk][tm * 4 + 1];
            float a2 = As[kk][tm * 4 + 2], a3 = As[kk][tm * 4 + 3];
            float b0 = Bs[kk][tn * 4 + 0], b1 = Bs[kk][tn * 4 + 1];
            float b2 = Bs[kk][tn * 4 + 2], b3 = Bs[kk][tn * 4 + 3];
            acc[0][0] = fmaf(a0, b0, acc[0][0]); acc[0][1] = fmaf(a0, b1, acc[0][1]);
            acc[0][2] = fmaf(a0, b2, acc[0][2]); acc[0][3] = fmaf(a0, b3, acc[0][3]);
            acc[1][0] = fmaf(a1, b0, acc[1][0]); acc[1][1] = fmaf(a1, b1, acc[1][1]);
            acc[1][2] = fmaf(a1, b2, acc[1][2]); acc[1][3] = fmaf(a1, b3, acc[1][3]);
            acc[2][0] = fmaf(a2, b0, acc[2][0]); acc[2][1] = fmaf(a2, b1, acc[2][1]);
            acc[2][2] = fmaf(a2, b2, acc[2][2]); acc[2][3] = fmaf(a2, b3, acc[2][3]);
            acc[3][0] = fmaf(a3, b0, acc[3][0]); acc[3][1] = fmaf(a3, b1, acc[3][1]);
            acc[3][2] = fmaf(a3, b2, acc[3][2]); acc[3][3] = fmaf(a3, b3, acc[3][3]);
        }
        __syncthreads();
    }
    #pragma unroll
    for (int i = 0; i < 4; i++) {
        int m = mB * GTM + tm * 4 + i;
        #pragma unroll
        for (int j = 0; j < 4; j++)
            g_WX[m * (3 * HID) + jB * GTN + tn * 4 + j] = acc[i][j];
    }
}

// GRU wavefront, 4 CTAs per node (quarter-split outputs).
// CTA (node, q) computes z,r,h for outputs t in [q*64, q*64+64).
// Intra-node exchange of pr = ph*r via g_PR + g_exc counter.
// Forward progress: all dependencies are on strictly smaller block indices.
__global__ __launch_bounds__(256) void k_gru(const int* __restrict__ edge,
                                             const float* __restrict__ bz,
                                             const float* __restrict__ br,
                                             const float* __restrict__ bh) {
    int grp  = blockIdx.x >> 2;
    int q    = blockIdx.x & 3;
    int node = grp + 1;
    int tid  = threadIdx.x;
    int o    = tid & 63;
    int ks   = tid >> 6;

    __shared__ float sph[HID];
    __shared__ float spr[HID];
    __shared__ float saz[4][64];
    __shared__ float sar[4][64];
    __shared__ float sch[4][64];
    __shared__ float sz[64];

    const float4* UZ4 = reinterpret_cast<const float4*>(g_UZP);
    const float4* UR4 = reinterpret_cast<const float4*>(g_URP);
    const float4* UH4 = reinterpret_cast<const float4*>(g_UHP);

    int p = edge[node * 2];

    // ---- parent-independent prefetch (off the critical path) ----
    int b1 = ((q * 4 + ks) * 16) * 64 + o;     // float4 tile base for this (q, ks)
    float4 uh[16];
    #pragma unroll
    for (int i = 0; i < 16; i++) uh[i] = UH4[b1 + i * 64];

    float wzx = 0.f, wrx = 0.f, whx = 0.f, bzv = 0.f, brv = 0.f, bhv = 0.f;
    if (tid < 64) {
        int t = q * 64 + o;
        wzx = g_WX[node * (3 * HID) + t];
        wrx = g_WX[node * (3 * HID) + HID + t];
        whx = g_WX[node * (3 * HID) + 2 * HID + t];
        bzv = bz[t]; brv = br[t]; bhv = bh[t];
    }

    // ---- wait for parent (all threads spin; acquire load) ----
    while (ld_acq(&g_flag[p]) < 4u) { }
    sph[tid] = __ldcg(&g_H[p * HID + tid]);
    __syncthreads();

    // ---- phase 1: z, r partial dots (K split 4-way across ks) ----
    const unsigned long long* sph64 = reinterpret_cast<const unsigned long long*>(sph);
    unsigned long long az0 = 0ull, az1 = 0ull, ar0 = 0ull, ar1 = 0ull;
    int pb = ks * 32;   // ull base index for this K-quarter
    #pragma unroll 8
    for (int kq = 0; kq < 16; kq++) {
        float4 uz = UZ4[b1 + kq * 64];
        float4 ur = UR4[b1 + kq * 64];
        unsigned long long p0 = sph64[pb + kq * 2];
        unsigned long long p1 = sph64[pb + kq * 2 + 1];
        az0 = ffma2(pk2(uz.x, uz.y), p0, az0);
        az1 = ffma2(pk2(uz.z, uz.w), p1, az1);
        ar0 = ffma2(pk2(ur.x, ur.y), p0, ar0);
        ar1 = ffma2(pk2(ur.z, ur.w), p1, ar1);
    }
    saz[ks][o] = hsum2(az0) + hsum2(az1);
    sar[ks][o] = hsum2(ar0) + hsum2(ar1);
    __syncthreads();

    if (tid < 64) {
        int t = q * 64 + o;
        float az = wzx + bzv + saz[0][o] + saz[1][o] + saz[2][o] + saz[3][o];
        float ar = wrx + brv + sar[0][o] + sar[1][o] + sar[2][o] + sar[3][o];
        float z = 1.f / (1.f + __expf(-az));
        float r = 1.f / (1.f + __expf(-ar));
        float prv = sph[t] * r;
        sz[o] = z;
        spr[t] = prv;
        g_PR[node * HID + t] = prv;
        __threadfence();
    }
    __syncthreads();
    if (tid == 0) atomicAdd(&g_exc[node], 1u);

    // ---- intra-node exchange: gather full pr vector ----
    while (ld_acq(&g_exc[node]) < 4u) { }
    if ((tid >> 6) != q) spr[tid] = __ldcg(&g_PR[node * HID + tid]);
    __syncthreads();

    // ---- phase 2: h partial dots with prefetched U_h ----
    const unsigned long long* spr64 = reinterpret_cast<const unsigned long long*>(spr);
    unsigned long long ah0 = 0ull, ah1 = 0ull;
    #pragma unroll
    for (int kq = 0; kq < 16; kq++) {
        unsigned long long p0 = spr64[pb + kq * 2];
        unsigned long long p1 = spr64[pb + kq * 2 + 1];
        ah0 = ffma2(pk2(uh[kq].x, uh[kq].y), p0, ah0);
        ah1 = ffma2(pk2(uh[kq].z, uh[kq].w), p1, ah1);
    }
    sch[ks][o] = hsum2(ah0) + hsum2(ah1);
    __syncthreads();

    if (tid < 64) {
        int t = q * 64 + o;
        float ahv = whx + bhv + sch[0][o] + sch[1][o] + sch[2][o] + sch[3][o];
        float c = tanhf(ahv);
        float z = sz[o];
        float h = z * sph[t] + (1.f - z) * c;
        g_H[node * HID + t] = h;
        __threadfence();
    }
    __syncthreads();
    if (tid == 0) atomicAdd(&g_flag[node], 1u);
}

// 32 partial leaf-max blocks
__global__ __launch_bounds__(HID) void k_leafmax(const int* __restrict__ leaf) {
    int b = blockIdx.x;
    int t = threadIdx.x;
    float m = -INFINITY;
    for (int i = b; i < N_LEAF; i += 32) {
        int n = leaf[i];
        m = fmaxf(m, g_H[n * HID + t]);
    }
    g_red[b * HID + t] = m;
}

__global__ __launch_bounds__(HID) void k_final(const float* __restrict__ Wout,
                                               const float* __restrict__ bout,
                                               const float* __restrict__ y,
                                               float* __restrict__ out, int out_size) {
    __shared__ float f[HID];
    __shared__ float red[HID];
    __shared__ float logits[NCLASS];
    int t = threadIdx.x;
    float m = g_red[t];
    #pragma unroll
    for (int b = 1; b < 32; b++) m = fmaxf(m, g_red[b * HID + t]);
    f[t] = m;
    __syncthreads();
    for (int c = 0; c < NCLASS; c++) {
        red[t] = Wout[c * HID + t] * f[t];
        __syncthreads();
        for (int s = HID / 2; s > 0; s >>= 1) {
            if (t < s) red[t] += red[t + s];
            __syncthreads();
        }
        if (t == 0) logits[c] = red[0] + bout[c];
        __syncthreads();
    }
    if (t == 0) {
        float mx = logits[0];
        for (int c = 1; c < NCLASS; c++) mx = fmaxf(mx, logits[c]);
        float e[NCLASS], s = 0.f;
        for (int c = 0; c < NCLASS; c++) { e[c] = expf(logits[c] - mx); s += e[c]; }
        float loss = 0.f;
        for (int c = 0; c < NCLASS; c++) {
            float pred = e[c] / s;
            float d = y[c] - pred;
            loss += d * d;
            if (c < out_size) out[c] = pred;
        }
        if (out_size > NCLASS) out[NCLASS] = loss;
    }
    for (int i = NCLASS + 1 + t; i < out_size; i += HID) out[i] = 0.f;
}

// ---------------- launch ----------------
extern "C" void kernel_launch(void* const* d_in, const int* in_sizes, int n_in,
                              void* d_out, int out_size) {
    const int*   tree  = (const int*)  d_in[0];
    const int*   edge  = (const int*)  d_in[1];
    const int*   leaf  = (const int*)  d_in[2];
    const float* y     = (const float*)d_in[3];
    const float* E     = (const float*)d_in[4];
    const float* W_z   = (const float*)d_in[5];
    const float* U_z   = (const float*)d_in[6];
    const float* b_z   = (const float*)d_in[7];
    const float* W_r   = (const float*)d_in[8];
    const float* U_r   = (const float*)d_in[9];
    const float* b_r   = (const float*)d_in[10];
    const float* W_h   = (const float*)d_in[11];
    const float* U_h   = (const float*)d_in[12];
    const float* b_h   = (const float*)d_in[13];
    const float* W_out = (const float*)d_in[14];
    const float* b_out = (const float*)d_in[15];
    float* out = (float*)d_out;

    k_zero_flags<<<(N_NODES + 255) / 256, 256>>>();

    dim3 tb(32, 8);
    dim3 tg((VOCAB + 31) / 32, HID / 32);
    k_transposeE<<<tg, tb>>>(E);

    k_packU<<<(3 * HID * HID + 255) / 256, 256>>>(U_z, U_r, U_h);

    k_gather<<<N_NODES, HID>>>(tree);

    dim3 gg(N_NODES / GTM, (3 * HID) / GTN);
    k_gemm<<<gg, 256>>>(W_z, W_r, W_h);

    k_gru<<<4 * (N_NODES - 1), 256>>>(edge, b_z, b_r, b_h);

    k_leafmax<<<32, HID>>>(leaf);
    k_final<<<1, HID>>>(W_out, b_out, y, out, out_size);
}